// round 10
// baseline (speedup 1.0000x reference)
#include <cuda_runtime.h>
#include <cuda_fp16.h>

#define NUM_NODES 150000
#define EMB_DIM   64
#define N_EDGES   4000000
#define SCAN_B    1024
#define SCAN_GRID ((NUM_NODES + SCAN_B - 1) / SCAN_B)   // 147
#define VEC_ELEMS (NUM_NODES * EMB_DIM / 4)             // 2.4M float4

__device__ __forceinline__ unsigned int h2_to_u32(__half2 h) {
    return *reinterpret_cast<unsigned int*>(&h);
}
__device__ __forceinline__ __half2 u32_to_h2(unsigned int u) {
    return *reinterpret_cast<__half2*>(&u);
}

// ---- scratch (static device globals; addresses taken ONLY in device code) ----
// y-buffers hold dis-prescaled embeddings: y = dis * embs (fp16)
__device__ __half g_y0[NUM_NODES * EMB_DIM];     // dis * w
__device__ __half g_y1[NUM_NODES * EMB_DIM];     // dis^2 * S1
__device__ __half g_y2[NUM_NODES * EMB_DIM];     // dis^2 * S2
__device__ int    g_csr[N_EDGES];                // row index only (4B)
__device__ int    g_offs[NUM_NODES + 1];
__device__ int    g_cur[NUM_NODES];
__device__ int    g_deg[NUM_NODES];
__device__ float  g_dis[NUM_NODES];              // deg^-1/2 (0 if deg==0)
__device__ float  g_dinv[NUM_NODES];             // deg^+1/2 (0 if deg==0)
__device__ int    g_part[SCAN_GRID];

__global__ void k_zero() {
    int i = blockIdx.x * blockDim.x + threadIdx.x;
    if (i < NUM_NODES) { g_deg[i] = 0; g_cur[i] = 0; }
}

__global__ void k_count_deg(const int* __restrict__ col) {
    int i = blockIdx.x * blockDim.x + threadIdx.x;
    if (i < N_EDGES) atomicAdd(&g_deg[col[i]], 1);
}

// ---- block-local exclusive scan of g_deg, + dis/dinv ----
__global__ void k_scan_block() {
    __shared__ int s[SCAN_B];
    int gid = blockIdx.x * SCAN_B + threadIdx.x;
    int v = (gid < NUM_NODES) ? g_deg[gid] : 0;
    s[threadIdx.x] = v;
    __syncthreads();
    for (int off = 1; off < SCAN_B; off <<= 1) {
        int t = (threadIdx.x >= off) ? s[threadIdx.x - off] : 0;
        __syncthreads();
        s[threadIdx.x] += t;
        __syncthreads();
    }
    if (gid < NUM_NODES) {
        g_offs[gid] = s[threadIdx.x] - v;
        g_dis[gid]  = (v > 0) ? rsqrtf((float)v) : 0.0f;
        g_dinv[gid] = (v > 0) ? sqrtf((float)v)  : 0.0f;
    }
    if (threadIdx.x == SCAN_B - 1) g_part[blockIdx.x] = s[SCAN_B - 1];
}

// ---- fused: scan_add (blocks 0..146) + y0 = dis*w -> fp16 (all blocks) ----
// blockDim == SCAN_B. y0 only needs g_dis (written by k_scan_block), so the
// two roles are independent and can share one launch.
__global__ void k_scan_add_y0(const float4* __restrict__ w) {
    int tid = threadIdx.x;

    // -- role A: add cross-block scan base (first SCAN_GRID blocks only) --
    if (blockIdx.x < SCAN_GRID) {
        __shared__ int red[SCAN_B / 32];
        __shared__ int base_s;
        int v = (tid < (int)blockIdx.x) ? g_part[tid] : 0;
        #pragma unroll
        for (int o = 16; o; o >>= 1) v += __shfl_down_sync(0xFFFFFFFFu, v, o);
        if ((tid & 31) == 0) red[tid >> 5] = v;
        __syncthreads();
        if (tid == 0) {
            int t = 0;
            for (int i = 0; i < SCAN_B / 32; ++i) t += red[i];
            base_s = t;
        }
        __syncthreads();
        int gid = blockIdx.x * SCAN_B + tid;
        if (gid < NUM_NODES) g_offs[gid] += base_s;
        if (gid == 0) g_offs[NUM_NODES] = N_EDGES;
    }

    // -- role B: y0 conversion (coalesced, all blocks) --
    int i = blockIdx.x * blockDim.x + tid;
    if (i < VEC_ELEMS) {
        float4 v = w[i];
        float d = g_dis[i >> 4];          // 16 consecutive threads share node
        uint2 h;
        h.x = h2_to_u32(__floats2half2_rn(d * v.x, d * v.y));
        h.y = h2_to_u32(__floats2half2_rn(d * v.z, d * v.w));
        ((uint2*)g_y0)[i] = h;
    }
}

// ---- fill CSR: row index only ----
__global__ void k_fill(const int* __restrict__ row, const int* __restrict__ col) {
    int e = blockIdx.x * blockDim.x + threadIdx.x;
    if (e >= N_EDGES) return;
    int c = col[e];
    int pos = g_offs[c] + atomicAdd(&g_cur[c], 1);
    g_csr[pos] = row[e];
}

// ---- add 8 fp16 values (one uint4) into 8 fp32 accumulators ----
__device__ __forceinline__ void sum8(float* a, uint4 hv) {
    float2 f0 = __half22float2(u32_to_h2(hv.x));
    float2 f1 = __half22float2(u32_to_h2(hv.y));
    float2 f2 = __half22float2(u32_to_h2(hv.z));
    float2 f3 = __half22float2(u32_to_h2(hv.w));
    a[0] += f0.x; a[1] += f0.y; a[2] += f1.x; a[3] += f1.y;
    a[4] += f2.x; a[5] += f2.y; a[6] += f3.x; a[7] += f3.y;
}

// ---- gather core with uint4 csr index loads (4 indices per LDG) ----
__device__ __forceinline__ void gather_core(const uint4* __restrict__ src,
                                            int s, int e, int lane, float* acc) {
    int j = s;
    // peel to 16B csr alignment
    while ((j & 3) && j < e) {
        int r = __ldg(&g_csr[j]);
        sum8(acc, __ldg(&src[r * 8 + lane]));
        ++j;
    }
    for (; j + 8 <= e; j += 8) {
        uint4 c0 = __ldg((const uint4*)&g_csr[j]);
        uint4 c1 = __ldg((const uint4*)&g_csr[j + 4]);
        uint4 v0 = __ldg(&src[c0.x * 8 + lane]);
        uint4 v1 = __ldg(&src[c0.y * 8 + lane]);
        uint4 v2 = __ldg(&src[c0.z * 8 + lane]);
        uint4 v3 = __ldg(&src[c0.w * 8 + lane]);
        uint4 v4 = __ldg(&src[c1.x * 8 + lane]);
        uint4 v5 = __ldg(&src[c1.y * 8 + lane]);
        uint4 v6 = __ldg(&src[c1.z * 8 + lane]);
        uint4 v7 = __ldg(&src[c1.w * 8 + lane]);
        sum8(acc, v0); sum8(acc, v1); sum8(acc, v2); sum8(acc, v3);
        sum8(acc, v4); sum8(acc, v5); sum8(acc, v6); sum8(acc, v7);
    }
    if (j + 4 <= e) {
        uint4 c0 = __ldg((const uint4*)&g_csr[j]);
        uint4 v0 = __ldg(&src[c0.x * 8 + lane]);
        uint4 v1 = __ldg(&src[c0.y * 8 + lane]);
        uint4 v2 = __ldg(&src[c0.z * 8 + lane]);
        uint4 v3 = __ldg(&src[c0.w * 8 + lane]);
        sum8(acc, v0); sum8(acc, v1); sum8(acc, v2); sum8(acc, v3);
        j += 4;
    }
    while (j < e) {
        int r = __ldg(&g_csr[j]);
        sum8(acc, __ldg(&src[r * 8 + lane]));
        ++j;
    }
}

// ---- layers 1 & 2: write ONLY the fp16 y for the next layer ----
__global__ void k_gather12(int layer) {
    int t = blockIdx.x * blockDim.x + threadIdx.x;
    int node = t >> 3, lane = t & 7;
    if (node >= NUM_NODES) return;

    const uint4* src = (layer == 1) ? (const uint4*)g_y0 : (const uint4*)g_y1;
    float acc[8] = {0.f, 0.f, 0.f, 0.f, 0.f, 0.f, 0.f, 0.f};
    gather_core(src, g_offs[node], g_offs[node + 1], lane, acc);

    float d = g_dis[node];
    float d2 = d * d;                       // y_next = dis^2 * S
    uint4 h;
    h.x = h2_to_u32(__floats2half2_rn(d2 * acc[0], d2 * acc[1]));
    h.y = h2_to_u32(__floats2half2_rn(d2 * acc[2], d2 * acc[3]));
    h.z = h2_to_u32(__floats2half2_rn(d2 * acc[4], d2 * acc[5]));
    h.w = h2_to_u32(__floats2half2_rn(d2 * acc[6], d2 * acc[7]));
    int i16 = node * 8 + lane;
    if (layer == 1) ((uint4*)g_y1)[i16] = h;
    else            ((uint4*)g_y2)[i16] = h;
}

// ---- layer 3 + fused mean: out = 0.25*(w + dinv*(y1+y2) + dis*S3) ----
__global__ void k_gather_final(const float4* __restrict__ w,
                               float4* __restrict__ out) {
    int t = blockIdx.x * blockDim.x + threadIdx.x;
    int node = t >> 3, lane = t & 7;
    if (node >= NUM_NODES) return;

    float acc[8] = {0.f, 0.f, 0.f, 0.f, 0.f, 0.f, 0.f, 0.f};
    gather_core((const uint4*)g_y2, g_offs[node], g_offs[node + 1], lane, acc);

    float d  = g_dis[node];
    float di = g_dinv[node];
    int i16 = node * 8 + lane;
    uint4 h1 = ((const uint4*)g_y1)[i16];
    uint4 h2 = ((const uint4*)g_y2)[i16];
    float e1[8], e2[8];
    {
        float2 a = __half22float2(u32_to_h2(h1.x)), b = __half22float2(u32_to_h2(h1.y));
        float2 c = __half22float2(u32_to_h2(h1.z)), dq = __half22float2(u32_to_h2(h1.w));
        e1[0]=a.x; e1[1]=a.y; e1[2]=b.x; e1[3]=b.y; e1[4]=c.x; e1[5]=c.y; e1[6]=dq.x; e1[7]=dq.y;
    }
    {
        float2 a = __half22float2(u32_to_h2(h2.x)), b = __half22float2(u32_to_h2(h2.y));
        float2 c = __half22float2(u32_to_h2(h2.z)), dq = __half22float2(u32_to_h2(h2.w));
        e2[0]=a.x; e2[1]=a.y; e2[2]=b.x; e2[3]=b.y; e2[4]=c.x; e2[5]=c.y; e2[6]=dq.x; e2[7]=dq.y;
    }

    int i = node * 16 + lane * 2;
    float4 a0 = w[i], a1 = w[i + 1];
    const float q = 0.25f;
    out[i] = make_float4(
        q * (a0.x + di * (e1[0] + e2[0]) + d * acc[0]),
        q * (a0.y + di * (e1[1] + e2[1]) + d * acc[1]),
        q * (a0.z + di * (e1[2] + e2[2]) + d * acc[2]),
        q * (a0.w + di * (e1[3] + e2[3]) + d * acc[3]));
    out[i + 1] = make_float4(
        q * (a1.x + di * (e1[4] + e2[4]) + d * acc[4]),
        q * (a1.y + di * (e1[5] + e2[5]) + d * acc[5]),
        q * (a1.z + di * (e1[6] + e2[6]) + d * acc[6]),
        q * (a1.w + di * (e1[7] + e2[7]) + d * acc[7]));
}

extern "C" void kernel_launch(void* const* d_in, const int* in_sizes, int n_in,
                              void* d_out, int out_size) {
    const int*   edge = (const int*)d_in[0];     // [2, N_EDGES] int32
    const int*   row  = edge;
    const int*   col  = edge + N_EDGES;
    const float* w    = (const float*)d_in[1];   // [NUM_NODES, EMB_DIM] f32
    float*       out  = (float*)d_out;

    const int B = 256;
    const int nodes_blk = (NUM_NODES + B - 1) / B;
    const int edges_blk = (N_EDGES + B - 1) / B;
    const int fuse_blk  = (VEC_ELEMS + SCAN_B - 1) / SCAN_B;   // covers both roles
    const long long gth = (long long)NUM_NODES * 8;
    const int gather_blk = (int)((gth + B - 1) / B);

    // ---- build phase ----
    k_zero<<<nodes_blk, B>>>();
    k_count_deg<<<edges_blk, B>>>(col);
    k_scan_block<<<SCAN_GRID, SCAN_B>>>();
    k_scan_add_y0<<<fuse_blk, SCAN_B>>>((const float4*)w);
    k_fill<<<edges_blk, B>>>(row, col);

    // ---- 3 propagation layers (natural node order: coalesced) ----
    k_gather12<<<gather_blk, B>>>(1);
    k_gather12<<<gather_blk, B>>>(2);
    k_gather_final<<<gather_blk, B>>>((const float4*)w, (float4*)out);
}

// round 11
// speedup vs baseline: 1.1181x; 1.1181x over previous
#include <cuda_runtime.h>
#include <cuda_fp16.h>

#define NUM_NODES 150000
#define EMB_DIM   64
#define N_EDGES   4000000
#define SCAN_B    1024
#define SCAN_GRID ((NUM_NODES + SCAN_B - 1) / SCAN_B)   // 147

__device__ __forceinline__ unsigned int h2_to_u32(__half2 h) {
    return *reinterpret_cast<unsigned int*>(&h);
}
__device__ __forceinline__ __half2 u32_to_h2(unsigned int u) {
    return *reinterpret_cast<__half2*>(&u);
}

// ---- scratch (static device globals; addresses taken ONLY in device code) ----
// y-buffers hold dis-prescaled embeddings: y = dis * embs (fp16)
__device__ __half g_y0[NUM_NODES * EMB_DIM];     // dis * w
__device__ __half g_y1[NUM_NODES * EMB_DIM];     // dis^2 * S1
__device__ __half g_y2[NUM_NODES * EMB_DIM];     // dis^2 * S2
__device__ int    g_csr[N_EDGES];                // row index only (4B)
__device__ int    g_offs[NUM_NODES + 1];
__device__ int    g_cur[NUM_NODES];              // fill cursor, pre-seeded to offs
__device__ int    g_deg[NUM_NODES];
__device__ float  g_dis[NUM_NODES];              // deg^-1/2 (0 if deg==0)
__device__ float  g_dinv[NUM_NODES];             // deg^+1/2 (0 if deg==0)
__device__ int    g_part[SCAN_GRID];

__global__ void k_zero() {
    int i = blockIdx.x * blockDim.x + threadIdx.x;
    if (i < NUM_NODES) g_deg[i] = 0;
}

__global__ void k_count_deg(const int* __restrict__ col) {
    int i = blockIdx.x * blockDim.x + threadIdx.x;
    if (i < N_EDGES) atomicAdd(&g_deg[col[i]], 1);
}

// ---- block-local exclusive scan of g_deg, + dis/dinv ----
__global__ void k_scan_block() {
    __shared__ int s[SCAN_B];
    int gid = blockIdx.x * SCAN_B + threadIdx.x;
    int v = (gid < NUM_NODES) ? g_deg[gid] : 0;
    s[threadIdx.x] = v;
    __syncthreads();
    for (int off = 1; off < SCAN_B; off <<= 1) {
        int t = (threadIdx.x >= off) ? s[threadIdx.x - off] : 0;
        __syncthreads();
        s[threadIdx.x] += t;
        __syncthreads();
    }
    if (gid < NUM_NODES) {
        g_offs[gid] = s[threadIdx.x] - v;
        g_dis[gid]  = (v > 0) ? rsqrtf((float)v) : 0.0f;
        g_dinv[gid] = (v > 0) ? sqrtf((float)v)  : 0.0f;
    }
    if (threadIdx.x == SCAN_B - 1) g_part[blockIdx.x] = s[SCAN_B - 1];
}

// ---- add cross-block base; also seed the fill cursor g_cur = final offs ----
__global__ void k_scan_add() {
    __shared__ int red[SCAN_B / 32];
    __shared__ int base_s;
    int tid = threadIdx.x;
    int v = (tid < (int)blockIdx.x) ? g_part[tid] : 0;
    #pragma unroll
    for (int o = 16; o; o >>= 1) v += __shfl_down_sync(0xFFFFFFFFu, v, o);
    if ((tid & 31) == 0) red[tid >> 5] = v;
    __syncthreads();
    if (tid == 0) {
        int t = 0;
        for (int i = 0; i < SCAN_B / 32; ++i) t += red[i];
        base_s = t;
    }
    __syncthreads();
    int gid = blockIdx.x * SCAN_B + tid;
    if (gid < NUM_NODES) {
        int o = g_offs[gid] + base_s;
        g_offs[gid] = o;
        g_cur[gid]  = o;       // fill cursor starts at segment base
    }
    if (gid == 0) g_offs[NUM_NODES] = N_EDGES;
}

// ---- y0 = dis * w (fp16), coalesced ----
__global__ void k_y0(const float4* __restrict__ w) {
    int i = blockIdx.x * blockDim.x + threadIdx.x;
    if (i < NUM_NODES * EMB_DIM / 4) {
        float4 v = w[i];
        float d = g_dis[i >> 4];          // 16 consecutive threads share node
        uint2 h;
        h.x = h2_to_u32(__floats2half2_rn(d * v.x, d * v.y));
        h.y = h2_to_u32(__floats2half2_rn(d * v.z, d * v.w));
        ((uint2*)g_y0)[i] = h;
    }
}

// ---- fill CSR: single atomic per edge (cursor pre-seeded to offs) ----
__global__ void k_fill(const int* __restrict__ row, const int* __restrict__ col) {
    int e = blockIdx.x * blockDim.x + threadIdx.x;
    if (e >= N_EDGES) return;
    int pos = atomicAdd(&g_cur[col[e]], 1);
    g_csr[pos] = row[e];
}

// ---- add 8 fp16 values (one uint4) into 8 fp32 accumulators ----
__device__ __forceinline__ void sum8(float* a, uint4 hv) {
    float2 f0 = __half22float2(u32_to_h2(hv.x));
    float2 f1 = __half22float2(u32_to_h2(hv.y));
    float2 f2 = __half22float2(u32_to_h2(hv.z));
    float2 f3 = __half22float2(u32_to_h2(hv.w));
    a[0] += f0.x; a[1] += f0.y; a[2] += f1.x; a[3] += f1.y;
    a[4] += f2.x; a[5] += f2.y; a[6] += f3.x; a[7] += f3.y;
}

// ---- gather core (R9 proven form: 8 independent scalar csr loads) ----
__device__ __forceinline__ void gather_core(const uint4* __restrict__ src,
                                            int s, int e, int lane, float* acc) {
    int j = s;
    for (; j + 8 <= e; j += 8) {
        int r0 = __ldg(&g_csr[j + 0]);
        int r1 = __ldg(&g_csr[j + 1]);
        int r2 = __ldg(&g_csr[j + 2]);
        int r3 = __ldg(&g_csr[j + 3]);
        int r4 = __ldg(&g_csr[j + 4]);
        int r5 = __ldg(&g_csr[j + 5]);
        int r6 = __ldg(&g_csr[j + 6]);
        int r7 = __ldg(&g_csr[j + 7]);
        uint4 v0 = __ldg(&src[r0 * 8 + lane]);
        uint4 v1 = __ldg(&src[r1 * 8 + lane]);
        uint4 v2 = __ldg(&src[r2 * 8 + lane]);
        uint4 v3 = __ldg(&src[r3 * 8 + lane]);
        uint4 v4 = __ldg(&src[r4 * 8 + lane]);
        uint4 v5 = __ldg(&src[r5 * 8 + lane]);
        uint4 v6 = __ldg(&src[r6 * 8 + lane]);
        uint4 v7 = __ldg(&src[r7 * 8 + lane]);
        sum8(acc, v0); sum8(acc, v1); sum8(acc, v2); sum8(acc, v3);
        sum8(acc, v4); sum8(acc, v5); sum8(acc, v6); sum8(acc, v7);
    }
    for (; j + 2 <= e; j += 2) {
        int ra = __ldg(&g_csr[j]);
        int rb = __ldg(&g_csr[j + 1]);
        uint4 va = __ldg(&src[ra * 8 + lane]);
        uint4 vb = __ldg(&src[rb * 8 + lane]);
        sum8(acc, va); sum8(acc, vb);
    }
    if (j < e) {
        int r = __ldg(&g_csr[j]);
        uint4 v = __ldg(&src[r * 8 + lane]);
        sum8(acc, v);
    }
}

// ---- layers 1 & 2: write ONLY the fp16 y for the next layer ----
__global__ void k_gather12(int layer) {
    int t = blockIdx.x * blockDim.x + threadIdx.x;
    int node = t >> 3, lane = t & 7;
    if (node >= NUM_NODES) return;

    const uint4* src = (layer == 1) ? (const uint4*)g_y0 : (const uint4*)g_y1;
    float acc[8] = {0.f, 0.f, 0.f, 0.f, 0.f, 0.f, 0.f, 0.f};
    gather_core(src, g_offs[node], g_offs[node + 1], lane, acc);

    float d = g_dis[node];
    float d2 = d * d;                       // y_next = dis^2 * S
    uint4 h;
    h.x = h2_to_u32(__floats2half2_rn(d2 * acc[0], d2 * acc[1]));
    h.y = h2_to_u32(__floats2half2_rn(d2 * acc[2], d2 * acc[3]));
    h.z = h2_to_u32(__floats2half2_rn(d2 * acc[4], d2 * acc[5]));
    h.w = h2_to_u32(__floats2half2_rn(d2 * acc[6], d2 * acc[7]));
    int i16 = node * 8 + lane;
    if (layer == 1) ((uint4*)g_y1)[i16] = h;
    else            ((uint4*)g_y2)[i16] = h;
}

// ---- layer 3 + fused mean: out = 0.25*(w + dinv*(y1+y2) + dis*S3) ----
__global__ void k_gather_final(const float4* __restrict__ w,
                               float4* __restrict__ out) {
    int t = blockIdx.x * blockDim.x + threadIdx.x;
    int node = t >> 3, lane = t & 7;
    if (node >= NUM_NODES) return;

    float acc[8] = {0.f, 0.f, 0.f, 0.f, 0.f, 0.f, 0.f, 0.f};
    gather_core((const uint4*)g_y2, g_offs[node], g_offs[node + 1], lane, acc);

    float d  = g_dis[node];
    float di = g_dinv[node];
    int i16 = node * 8 + lane;
    uint4 h1 = ((const uint4*)g_y1)[i16];
    uint4 h2 = ((const uint4*)g_y2)[i16];
    float e1[8], e2[8];
    {
        float2 a = __half22float2(u32_to_h2(h1.x)), b = __half22float2(u32_to_h2(h1.y));
        float2 c = __half22float2(u32_to_h2(h1.z)), dq = __half22float2(u32_to_h2(h1.w));
        e1[0]=a.x; e1[1]=a.y; e1[2]=b.x; e1[3]=b.y; e1[4]=c.x; e1[5]=c.y; e1[6]=dq.x; e1[7]=dq.y;
    }
    {
        float2 a = __half22float2(u32_to_h2(h2.x)), b = __half22float2(u32_to_h2(h2.y));
        float2 c = __half22float2(u32_to_h2(h2.z)), dq = __half22float2(u32_to_h2(h2.w));
        e2[0]=a.x; e2[1]=a.y; e2[2]=b.x; e2[3]=b.y; e2[4]=c.x; e2[5]=c.y; e2[6]=dq.x; e2[7]=dq.y;
    }

    int i = node * 16 + lane * 2;
    float4 a0 = w[i], a1 = w[i + 1];
    const float q = 0.25f;
    out[i] = make_float4(
        q * (a0.x + di * (e1[0] + e2[0]) + d * acc[0]),
        q * (a0.y + di * (e1[1] + e2[1]) + d * acc[1]),
        q * (a0.z + di * (e1[2] + e2[2]) + d * acc[2]),
        q * (a0.w + di * (e1[3] + e2[3]) + d * acc[3]));
    out[i + 1] = make_float4(
        q * (a1.x + di * (e1[4] + e2[4]) + d * acc[4]),
        q * (a1.y + di * (e1[5] + e2[5]) + d * acc[5]),
        q * (a1.z + di * (e1[6] + e2[6]) + d * acc[6]),
        q * (a1.w + di * (e1[7] + e2[7]) + d * acc[7]));
}

extern "C" void kernel_launch(void* const* d_in, const int* in_sizes, int n_in,
                              void* d_out, int out_size) {
    const int*   edge = (const int*)d_in[0];     // [2, N_EDGES] int32
    const int*   row  = edge;
    const int*   col  = edge + N_EDGES;
    const float* w    = (const float*)d_in[1];   // [NUM_NODES, EMB_DIM] f32
    float*       out  = (float*)d_out;

    const int B = 256;
    const int nodes_blk = (NUM_NODES + B - 1) / B;
    const int edges_blk = (N_EDGES + B - 1) / B;
    const int vec_blk   = (NUM_NODES * EMB_DIM / 4 + B - 1) / B;
    const long long gth = (long long)NUM_NODES * 8;
    const int gather_blk = (int)((gth + B - 1) / B);

    // ---- build phase ----
    k_zero<<<nodes_blk, B>>>();
    k_count_deg<<<edges_blk, B>>>(col);
    k_scan_block<<<SCAN_GRID, SCAN_B>>>();
    k_scan_add<<<SCAN_GRID, SCAN_B>>>();
    k_y0<<<vec_blk, B>>>((const float4*)w);
    k_fill<<<edges_blk, B>>>(row, col);

    // ---- 3 propagation layers (natural node order: coalesced) ----
    k_gather12<<<gather_blk, B>>>(1);
    k_gather12<<<gather_blk, B>>>(2);
    k_gather_final<<<gather_blk, B>>>((const float4*)w, (float4*)out);
}

// round 12
// speedup vs baseline: 1.1528x; 1.0311x over previous
#include <cuda_runtime.h>
#include <cuda_fp16.h>

#define NUM_NODES 150000
#define EMB_DIM   64
#define N_EDGES   4000000
#define SCAN_B    1024
#define SCAN_GRID ((NUM_NODES + SCAN_B - 1) / SCAN_B)   // 147
#define VEC_ELEMS (NUM_NODES * EMB_DIM / 4)             // 2.4M float4

__device__ __forceinline__ unsigned int h2_to_u32(__half2 h) {
    return *reinterpret_cast<unsigned int*>(&h);
}
__device__ __forceinline__ __half2 u32_to_h2(unsigned int u) {
    return *reinterpret_cast<__half2*>(&u);
}

// ---- scratch (static device globals; addresses taken ONLY in device code) ----
// y-buffers hold dis-prescaled embeddings: y = dis * embs (fp16)
__device__ __half g_y0[NUM_NODES * EMB_DIM];     // dis * w
__device__ __half g_y1[NUM_NODES * EMB_DIM];     // dis^2 * S1
__device__ __half g_y2[NUM_NODES * EMB_DIM];     // dis^2 * S2
__device__ int    g_csr[N_EDGES];                // row index only (4B)
__device__ int    g_offs[NUM_NODES + 1];
__device__ int    g_cur[NUM_NODES];              // fill cursor, pre-seeded to offs
__device__ int    g_deg[NUM_NODES];
__device__ float  g_dis[NUM_NODES];              // deg^-1/2 (0 if deg==0)
__device__ float  g_dinv[NUM_NODES];             // deg^+1/2 (0 if deg==0)
__device__ int    g_part[SCAN_GRID];

__global__ void k_zero() {
    int i = blockIdx.x * blockDim.x + threadIdx.x;
    if (i < NUM_NODES) g_deg[i] = 0;
}

__global__ void k_count_deg(const int* __restrict__ col) {
    int i = blockIdx.x * blockDim.x + threadIdx.x;
    if (i < N_EDGES) atomicAdd(&g_deg[col[i]], 1);
}

// ---- block-local exclusive scan of g_deg, + dis/dinv ----
__global__ void k_scan_block() {
    __shared__ int s[SCAN_B];
    int gid = blockIdx.x * SCAN_B + threadIdx.x;
    int v = (gid < NUM_NODES) ? g_deg[gid] : 0;
    s[threadIdx.x] = v;
    __syncthreads();
    for (int off = 1; off < SCAN_B; off <<= 1) {
        int t = (threadIdx.x >= off) ? s[threadIdx.x - off] : 0;
        __syncthreads();
        s[threadIdx.x] += t;
        __syncthreads();
    }
    if (gid < NUM_NODES) {
        g_offs[gid] = s[threadIdx.x] - v;
        g_dis[gid]  = (v > 0) ? rsqrtf((float)v) : 0.0f;
        g_dinv[gid] = (v > 0) ? sqrtf((float)v)  : 0.0f;
    }
    if (threadIdx.x == SCAN_B - 1) g_part[blockIdx.x] = s[SCAN_B - 1];
}

// ---- add cross-block base; also seed the fill cursor g_cur = final offs ----
__global__ void k_scan_add() {
    __shared__ int red[SCAN_B / 32];
    __shared__ int base_s;
    int tid = threadIdx.x;
    int v = (tid < (int)blockIdx.x) ? g_part[tid] : 0;
    #pragma unroll
    for (int o = 16; o; o >>= 1) v += __shfl_down_sync(0xFFFFFFFFu, v, o);
    if ((tid & 31) == 0) red[tid >> 5] = v;
    __syncthreads();
    if (tid == 0) {
        int t = 0;
        for (int i = 0; i < SCAN_B / 32; ++i) t += red[i];
        base_s = t;
    }
    __syncthreads();
    int gid = blockIdx.x * SCAN_B + tid;
    if (gid < NUM_NODES) {
        int o = g_offs[gid] + base_s;
        g_offs[gid] = o;
        g_cur[gid]  = o;       // fill cursor starts at segment base
    }
    if (gid == 0) g_offs[NUM_NODES] = N_EDGES;
}

// ---- fused: CSR fill (all blocks) + y0 = dis*w -> fp16 (first blocks) ----
// The two roles are independent (different hardware resources: fill is
// L2-atomic bound, y0 is streaming bound) and both depend only on k_scan_add.
// Co-scheduling them in one launch overlaps their latencies.
__global__ void k_y0_fill(const float4* __restrict__ w,
                          const int* __restrict__ row,
                          const int* __restrict__ col) {
    int i = blockIdx.x * blockDim.x + threadIdx.x;

    // role A: y0 conversion (first VEC_ELEMS threads)
    if (i < VEC_ELEMS) {
        float4 v = w[i];
        float d = g_dis[i >> 4];          // 16 consecutive threads share node
        uint2 h;
        h.x = h2_to_u32(__floats2half2_rn(d * v.x, d * v.y));
        h.y = h2_to_u32(__floats2half2_rn(d * v.z, d * v.w));
        ((uint2*)g_y0)[i] = h;
    }

    // role B: CSR fill (first N_EDGES threads; single atomic per edge)
    if (i < N_EDGES) {
        int pos = atomicAdd(&g_cur[col[i]], 1);
        g_csr[pos] = row[i];
    }
}

// ---- add 8 fp16 values (one uint4) into 8 fp32 accumulators ----
__device__ __forceinline__ void sum8(float* a, uint4 hv) {
    float2 f0 = __half22float2(u32_to_h2(hv.x));
    float2 f1 = __half22float2(u32_to_h2(hv.y));
    float2 f2 = __half22float2(u32_to_h2(hv.z));
    float2 f3 = __half22float2(u32_to_h2(hv.w));
    a[0] += f0.x; a[1] += f0.y; a[2] += f1.x; a[3] += f1.y;
    a[4] += f2.x; a[5] += f2.y; a[6] += f3.x; a[7] += f3.y;
}

// ---- gather core (R9 proven form: 8 independent scalar csr loads) ----
__device__ __forceinline__ void gather_core(const uint4* __restrict__ src,
                                            int s, int e, int lane, float* acc) {
    int j = s;
    for (; j + 8 <= e; j += 8) {
        int r0 = __ldg(&g_csr[j + 0]);
        int r1 = __ldg(&g_csr[j + 1]);
        int r2 = __ldg(&g_csr[j + 2]);
        int r3 = __ldg(&g_csr[j + 3]);
        int r4 = __ldg(&g_csr[j + 4]);
        int r5 = __ldg(&g_csr[j + 5]);
        int r6 = __ldg(&g_csr[j + 6]);
        int r7 = __ldg(&g_csr[j + 7]);
        uint4 v0 = __ldg(&src[r0 * 8 + lane]);
        uint4 v1 = __ldg(&src[r1 * 8 + lane]);
        uint4 v2 = __ldg(&src[r2 * 8 + lane]);
        uint4 v3 = __ldg(&src[r3 * 8 + lane]);
        uint4 v4 = __ldg(&src[r4 * 8 + lane]);
        uint4 v5 = __ldg(&src[r5 * 8 + lane]);
        uint4 v6 = __ldg(&src[r6 * 8 + lane]);
        uint4 v7 = __ldg(&src[r7 * 8 + lane]);
        sum8(acc, v0); sum8(acc, v1); sum8(acc, v2); sum8(acc, v3);
        sum8(acc, v4); sum8(acc, v5); sum8(acc, v6); sum8(acc, v7);
    }
    for (; j + 2 <= e; j += 2) {
        int ra = __ldg(&g_csr[j]);
        int rb = __ldg(&g_csr[j + 1]);
        uint4 va = __ldg(&src[ra * 8 + lane]);
        uint4 vb = __ldg(&src[rb * 8 + lane]);
        sum8(acc, va); sum8(acc, vb);
    }
    if (j < e) {
        int r = __ldg(&g_csr[j]);
        uint4 v = __ldg(&src[r * 8 + lane]);
        sum8(acc, v);
    }
}

// ---- layers 1 & 2: write ONLY the fp16 y for the next layer ----
__global__ void k_gather12(int layer) {
    int t = blockIdx.x * blockDim.x + threadIdx.x;
    int node = t >> 3, lane = t & 7;
    if (node >= NUM_NODES) return;

    const uint4* src = (layer == 1) ? (const uint4*)g_y0 : (const uint4*)g_y1;
    float acc[8] = {0.f, 0.f, 0.f, 0.f, 0.f, 0.f, 0.f, 0.f};
    gather_core(src, g_offs[node], g_offs[node + 1], lane, acc);

    float d = g_dis[node];
    float d2 = d * d;                       // y_next = dis^2 * S
    uint4 h;
    h.x = h2_to_u32(__floats2half2_rn(d2 * acc[0], d2 * acc[1]));
    h.y = h2_to_u32(__floats2half2_rn(d2 * acc[2], d2 * acc[3]));
    h.z = h2_to_u32(__floats2half2_rn(d2 * acc[4], d2 * acc[5]));
    h.w = h2_to_u32(__floats2half2_rn(d2 * acc[6], d2 * acc[7]));
    int i16 = node * 8 + lane;
    if (layer == 1) ((uint4*)g_y1)[i16] = h;
    else            ((uint4*)g_y2)[i16] = h;
}

// ---- layer 3 + fused mean: out = 0.25*(w + dinv*(y1+y2) + dis*S3) ----
__global__ void k_gather_final(const float4* __restrict__ w,
                               float4* __restrict__ out) {
    int t = blockIdx.x * blockDim.x + threadIdx.x;
    int node = t >> 3, lane = t & 7;
    if (node >= NUM_NODES) return;

    float acc[8] = {0.f, 0.f, 0.f, 0.f, 0.f, 0.f, 0.f, 0.f};
    gather_core((const uint4*)g_y2, g_offs[node], g_offs[node + 1], lane, acc);

    float d  = g_dis[node];
    float di = g_dinv[node];
    int i16 = node * 8 + lane;
    uint4 h1 = ((const uint4*)g_y1)[i16];
    uint4 h2 = ((const uint4*)g_y2)[i16];
    float e1[8], e2[8];
    {
        float2 a = __half22float2(u32_to_h2(h1.x)), b = __half22float2(u32_to_h2(h1.y));
        float2 c = __half22float2(u32_to_h2(h1.z)), dq = __half22float2(u32_to_h2(h1.w));
        e1[0]=a.x; e1[1]=a.y; e1[2]=b.x; e1[3]=b.y; e1[4]=c.x; e1[5]=c.y; e1[6]=dq.x; e1[7]=dq.y;
    }
    {
        float2 a = __half22float2(u32_to_h2(h2.x)), b = __half22float2(u32_to_h2(h2.y));
        float2 c = __half22float2(u32_to_h2(h2.z)), dq = __half22float2(u32_to_h2(h2.w));
        e2[0]=a.x; e2[1]=a.y; e2[2]=b.x; e2[3]=b.y; e2[4]=c.x; e2[5]=c.y; e2[6]=dq.x; e2[7]=dq.y;
    }

    int i = node * 16 + lane * 2;
    float4 a0 = w[i], a1 = w[i + 1];
    const float q = 0.25f;
    out[i] = make_float4(
        q * (a0.x + di * (e1[0] + e2[0]) + d * acc[0]),
        q * (a0.y + di * (e1[1] + e2[1]) + d * acc[1]),
        q * (a0.z + di * (e1[2] + e2[2]) + d * acc[2]),
        q * (a0.w + di * (e1[3] + e2[3]) + d * acc[3]));
    out[i + 1] = make_float4(
        q * (a1.x + di * (e1[4] + e2[4]) + d * acc[4]),
        q * (a1.y + di * (e1[5] + e2[5]) + d * acc[5]),
        q * (a1.z + di * (e1[6] + e2[6]) + d * acc[6]),
        q * (a1.w + di * (e1[7] + e2[7]) + d * acc[7]));
}

extern "C" void kernel_launch(void* const* d_in, const int* in_sizes, int n_in,
                              void* d_out, int out_size) {
    const int*   edge = (const int*)d_in[0];     // [2, N_EDGES] int32
    const int*   row  = edge;
    const int*   col  = edge + N_EDGES;
    const float* w    = (const float*)d_in[1];   // [NUM_NODES, EMB_DIM] f32
    float*       out  = (float*)d_out;

    const int B = 256;
    const int nodes_blk = (NUM_NODES + B - 1) / B;
    const int edges_blk = (N_EDGES + B - 1) / B;   // covers both fused roles
    const long long gth = (long long)NUM_NODES * 8;
    const int gather_blk = (int)((gth + B - 1) / B);

    // ---- build phase ----
    k_zero<<<nodes_blk, B>>>();
    k_count_deg<<<edges_blk, B>>>(col);
    k_scan_block<<<SCAN_GRID, SCAN_B>>>();
    k_scan_add<<<SCAN_GRID, SCAN_B>>>();
    k_y0_fill<<<edges_blk, B>>>((const float4*)w, row, col);

    // ---- 3 propagation layers (natural node order: coalesced) ----
    k_gather12<<<gather_blk, B>>>(1);
    k_gather12<<<gather_blk, B>>>(2);
    k_gather_final<<<gather_blk, B>>>((const float4*)w, (float4*)out);
}